// round 11
// baseline (speedup 1.0000x reference)
#include <cuda_runtime.h>

#define BATCH 4
#define NPTS  4096
#define KPN   512
#define KNN   32

#define TPB   256
#define RC    256             // ref chunk per block (smem staged)
#define NRC   (NPTS / RC)     // 16
#define QT    2048            // queries per block (8 per thread)
#define NQT   (NPTS / QT)     // 2
#define NBLK  (2 * BATCH * NQT * NRC)  // 256 blocks
#define INFV  3.0e38f

// Encoded global mins: [0,16384) per-tgt-point (row), [16384,32768) per-src
// (col). Descending encoding => atomicMax == float-min, 0 == empty.
// Zero at module load; fin_kernel re-zeros each entry after reading, so each
// launch starts from identical state (deterministic, graph-replay safe).
__device__ unsigned g_minbits[2 * BATCH * NPTS];

__device__ __forceinline__ unsigned enc_desc(float f) {
    unsigned u = __float_as_uint(f);
    return (u & 0x80000000u) ? u : ~(u | 0x80000000u);
}
__device__ __forceinline__ float dec_desc(unsigned e) {
    unsigned s = ~e;
    unsigned u = (s & 0x80000000u) ? (s ^ 0x80000000u) : ~s;
    return __uint_as_float(u);
}

// Packed f32x2 FMA (sm_103a, PTX-only; no packed min exists)
__device__ __forceinline__ float2 ffma2(float2 a, float2 b, float2 c) {
    float2 d;
    asm("fma.rn.f32x2 %0, %1, %2, %3;"
        : "=l"(*reinterpret_cast<unsigned long long*>(&d))
        : "l"(*reinterpret_cast<const unsigned long long*>(&a)),
          "l"(*reinterpret_cast<const unsigned long long*>(&b)),
          "l"(*reinterpret_cast<const unsigned long long*>(&c)));
    return d;
}

// ---------------------------------------------------------------------------
// Kernel 1: symmetric min pass. Each block: 2048 reg-resident "queries"
// (8/thread, packed pairs, pre-scaled by -2, norm deferred) x 256 smem-staged
// "refs" (duplicated-lane packs carrying their norm as the FMA-chain bias).
// All lanes read the SAME ref per iter -> LDS broadcast (1 wavefront), no
// skew, no in-loop smem writes. Accumulate min of (rn - 2 q.r) in registers;
// add qn at the end; fold into g_minbits via encoded RED.MAX.
//   pass 0 (row): Q=tgt (gts),  R=src_tr (preds), out [0, 16384)
//   pass 1 (col): Q=src_tr,     R=tgt,            out [16384, 32768)
// grid = 2 * BATCH * NQT * NRC = 256 blocks x 256 threads, 256-iter loop.
// ---------------------------------------------------------------------------
__global__ void __launch_bounds__(TPB) min_kernel(const float* __restrict__ tgt,
                                                  const float* __restrict__ src,
                                                  float* __restrict__ out) {
    __shared__ float4 sR1[RC];   // (rx,rx,ry,ry)
    __shared__ float4 sR2[RC];   // (rz,rz,rn,rn)

    int bid  = blockIdx.x;
    int rc   = bid & (NRC - 1);        // ref chunk 0..15
    int qt   = (bid >> 4) & (NQT - 1); // query tile 0..1
    int b    = (bid >> 5) & 3;         // batch
    int pass = bid >> 7;               // 0 = row, 1 = col

    int t = threadIdx.x;
    if (bid == 0 && t == 0) { out[0] = 0.0f; out[1] = 0.0f; }

    const float* Q = (pass == 0 ? tgt : src) + b * 3 * NPTS;
    const float* R = (pass == 0 ? src : tgt) + b * 3 * NPTS;
    unsigned* om = g_minbits + pass * BATCH * NPTS + b * NPTS;

    // Stage ref chunk: one ref per thread, duplicated lanes + norm as bias.
    {
        int j = rc * RC + t;
        float rx = R[j], ry = R[NPTS + j], rz = R[2 * NPTS + j];
        float rn = fmaf(rx, rx, fmaf(ry, ry, rz * rz));
        sR1[t] = make_float4(rx, rx, ry, ry);
        sR2[t] = make_float4(rz, rz, rn, rn);
    }
    __syncthreads();

    // 8 queries per thread as 4 packed pairs; pre-scaled by -2; norms kept
    // separately (deferred to the end — min of (rn - 2q.r) + qn afterwards).
    float2 qx[4], qy[4], qz[4], qn[4];
    float  m[8];
    int q0 = qt * QT + t;
    #pragma unroll
    for (int jp = 0; jp < 4; jp++) {
        int qa = q0 + (2 * jp) * TPB;
        int qc = q0 + (2 * jp + 1) * TPB;
        float ax = Q[qa], ay = Q[NPTS + qa], az = Q[2 * NPTS + qa];
        float cx = Q[qc], cy = Q[NPTS + qc], cz = Q[2 * NPTS + qc];
        qn[jp] = make_float2(fmaf(ax, ax, fmaf(ay, ay, az * az)),
                             fmaf(cx, cx, fmaf(cy, cy, cz * cz)));
        qx[jp] = make_float2(-2.0f * ax, -2.0f * cx);
        qy[jp] = make_float2(-2.0f * ay, -2.0f * cy);
        qz[jp] = make_float2(-2.0f * az, -2.0f * cz);
        m[2 * jp] = INFV; m[2 * jp + 1] = INFV;
    }

    // Main loop: broadcast one ref per iteration to all lanes.
    #pragma unroll 8
    for (int i = 0; i < RC; i++) {
        float4 r1 = sR1[i];                      // broadcast, 1 wavefront
        float4 r2 = sR2[i];
        float2 rx = make_float2(r1.x, r1.y);
        float2 ry = make_float2(r1.z, r1.w);
        float2 rz = make_float2(r2.x, r2.y);
        float2 rn = make_float2(r2.z, r2.w);

        #pragma unroll
        for (int jp = 0; jp < 4; jp++) {
            float2 s = ffma2(qx[jp], rx, ffma2(qy[jp], ry, ffma2(qz[jp], rz, rn)));
            m[2 * jp]     = fminf(m[2 * jp],     s.x);
            m[2 * jp + 1] = fminf(m[2 * jp + 1], s.y);
        }
    }

    // Add deferred query norm, fold into global mins (RED.MAX, no return).
    #pragma unroll
    for (int jp = 0; jp < 4; jp++) {
        atomicMax(&om[q0 + (2 * jp) * TPB],     enc_desc(m[2 * jp]     + qn[jp].x));
        atomicMax(&om[q0 + (2 * jp + 1) * TPB], enc_desc(m[2 * jp + 1] + qn[jp].y));
    }
}

// ---------------------------------------------------------------------------
__device__ __forceinline__ float2 block_reduce2(float2 v) {
    __shared__ float2 sh[32];
    int lane = threadIdx.x & 31;
    int wid  = threadIdx.x >> 5;
    #pragma unroll
    for (int o = 16; o; o >>= 1) {
        v.x += __shfl_down_sync(0xffffffffu, v.x, o);
        v.y += __shfl_down_sync(0xffffffffu, v.y, o);
    }
    if (lane == 0) sh[wid] = v;
    __syncthreads();
    if (wid == 0) {
        v = (lane < (int)(blockDim.x >> 5)) ? sh[lane] : make_float2(0.0f, 0.0f);
        #pragma unroll
        for (int o = 16; o; o >>= 1) {
            v.x += __shfl_down_sync(0xffffffffu, v.x, o);
            v.y += __shfl_down_sync(0xffffffffu, v.y, o);
        }
    }
    return v;
}

// ---------------------------------------------------------------------------
// Kernel 2: finalize (R7 structure — all loads hoisted and independent).
// grid = 256 blocks x 128 threads = 32768 (one per min entry).
// ---------------------------------------------------------------------------
__global__ void __launch_bounds__(128) fin_kernel(const float* __restrict__ sk,
                                                  const float* __restrict__ tk,
                                                  const float* __restrict__ Rot,
                                                  const float* __restrict__ Tr,
                                                  const float* __restrict__ sknn,
                                                  const float* __restrict__ tknn,
                                                  float* __restrict__ out) {
    int i = blockIdx.x * 128 + threadIdx.x;  // 0..32767

    unsigned e = g_minbits[i];

    const int TOT4 = BATCH * 3 * KPN * KNN / 4;  // 49152
    const float4* s4 = (const float4*)sknn;
    const float4* t4 = (const float4*)tknn;
    float4 a0 = s4[i];
    float4 b0 = t4[i];
    bool has2 = (i + 32768) < TOT4;              // i < 16384
    int j2 = has2 ? (i + 32768) : i;
    float4 a1 = s4[j2];
    float4 b1 = t4[j2];

    g_minbits[i] = 0;                            // reset for next replay

    float d = dec_desc(e);
    const float c = 0.01f;
    float h = (d < c) ? (0.5f * d * d) : fmaf(c, d, -0.5f * c * c);

    float d0 = a0.x - b0.x, d1 = a0.y - b0.y, d2 = a0.z - b0.z, d3 = a0.w - b0.w;
    float acc = fmaf(d0, d0, fmaf(d1, d1, fmaf(d2, d2, d3 * d3)));
    if (has2) {
        float e0 = a1.x - b1.x, e1 = a1.y - b1.y, e2 = a1.z - b1.z, e3 = a1.w - b1.w;
        acc += fmaf(e0, e0, fmaf(e1, e1, fmaf(e2, e2, e3 * e3)));
    }
    acc *= (1.0f / (float)KNN);

    if (i < BATCH * KPN) {
        int kb = i >> 9;
        int p  = i & (KPN - 1);
        const float* Rb  = Rot + kb * 9;
        const float* tb  = Tr + kb * 3;
        const float* skb = sk + kb * 3 * KPN;
        const float* tkb = tk + kb * 3 * KPN;
        float px = skb[p], py = skb[KPN + p], pz = skb[2 * KPN + p];
        #pragma unroll
        for (int cd = 0; cd < 3; cd++) {
            float wv = fmaf(Rb[cd * 3 + 0], px,
                       fmaf(Rb[cd * 3 + 1], py,
                       fmaf(Rb[cd * 3 + 2], pz, tb[cd])))
                       - tkb[cd * KPN + p];
            acc = fmaf(wv, wv, acc);
        }
    }

    float2 sums = block_reduce2(make_float2(acc, h));
    if (threadIdx.x == 0) {
        atomicAdd(&out[0], sums.x);
        atomicAdd(&out[1], sums.y);
    }
}

// ---------------------------------------------------------------------------
extern "C" void kernel_launch(void* const* d_in, const int* in_sizes, int n_in,
                              void* d_out, int out_size) {
    const float* src_kp  = (const float*)d_in[0];  // (B,3,KP)
    const float* tgt_kp  = (const float*)d_in[1];  // (B,3,KP)
    const float* rot     = (const float*)d_in[2];  // (B,3,3)
    const float* tra     = (const float*)d_in[3];  // (B,3)
    const float* src_knn = (const float*)d_in[4];  // (B,3,KP,K)
    const float* tgt_knn = (const float*)d_in[5];  // (B,3,KP,K)
    // d_in[6] = k (constant 32, hardcoded)
    const float* src_tr  = (const float*)d_in[7];  // (B,3,N) preds
    const float* tgt     = (const float*)d_in[8];  // (B,3,N) gts
    float* out = (float*)d_out;                    // out[0]=nbh, out[1]=gal

    min_kernel<<<NBLK, TPB>>>(tgt, src_tr, out);
    fin_kernel<<<256, 128>>>(src_kp, tgt_kp, rot, tra, src_knn, tgt_knn, out);
}

// round 13
// speedup vs baseline: 1.1381x; 1.1381x over previous
#include <cuda_runtime.h>

#define BATCH 4
#define NPTS  4096
#define KPN   512
#define KNN   32

#define TPB   256
#define BSL   128             // refs per block slice (inner loop length)
#define NBS   (NPTS / BSL)    // 32
#define ATILE 2048            // queries per block (8 per thread)
#define NAT   (NPTS / ATILE)  // 2
#define NBLK  (BATCH * NAT * NBS)  // 256 blocks
#define INFV  3.0e38f

// Encoded global mins: [0,16384) row (per-tgt-point), [16384,32768) col
// (per-src-point). Descending encoding => atomicMax == float-min, 0 == empty.
// Zero at module load; fin_kernel re-zeros each entry after reading.
__device__ unsigned g_minbits[2 * BATCH * NPTS];

__device__ __forceinline__ unsigned enc_desc(float f) {
    unsigned u = __float_as_uint(f);
    return (u & 0x80000000u) ? u : ~(u | 0x80000000u);
}
__device__ __forceinline__ float dec_desc(unsigned e) {
    unsigned s = ~e;
    unsigned u = (s & 0x80000000u) ? (s ^ 0x80000000u) : ~s;
    return __uint_as_float(u);
}

// Packed f32x2 ops (sm_103a, PTX-only; packed min does NOT exist)
__device__ __forceinline__ float2 ffma2(float2 a, float2 b, float2 c) {
    float2 d;
    asm("fma.rn.f32x2 %0, %1, %2, %3;"
        : "=l"(*reinterpret_cast<unsigned long long*>(&d))
        : "l"(*reinterpret_cast<const unsigned long long*>(&a)),
          "l"(*reinterpret_cast<const unsigned long long*>(&b)),
          "l"(*reinterpret_cast<const unsigned long long*>(&c)));
    return d;
}
__device__ __forceinline__ float2 fadd2(float2 a, float2 b) {
    float2 d;
    asm("add.rn.f32x2 %0, %1, %2;"
        : "=l"(*reinterpret_cast<unsigned long long*>(&d))
        : "l"(*reinterpret_cast<const unsigned long long*>(&a)),
          "l"(*reinterpret_cast<const unsigned long long*>(&b)));
    return d;
}

// ---------------------------------------------------------------------------
// Kernel 1: dual-use tile pass, broadcast refs.
// Block = 2048 reg-resident queries (8/thread, packed, pre-scaled -2) x 128
// smem refs. Per iteration ALL lanes process the SAME ref (LDS broadcast, 1
// wavefront): 12 FFMA2 + 4 ADD2 (full-dist bias) + 8 row FMNMX + 7-min tree +
// clamp + one REDUX.MIN.U32 (dists >= 0 after clamp, so uint order == float
// order) + lane0 STS. No skew, no smem RMW chain.
// grid = BATCH * NAT * NBS = 256 blocks x 256 threads.
// ---------------------------------------------------------------------------
__global__ void __launch_bounds__(TPB) min_kernel(const float* __restrict__ A,
                                                  const float* __restrict__ B,
                                                  float* __restrict__ out) {
    __shared__ float4 sR1[BSL];        // (bx,bx,by,by)
    __shared__ float4 sR2[BSL];        // (bz,bz,bn,bn)
    __shared__ float  cmin[8][BSL];    // per-warp col mins (one STS/iter/warp)

    int bid = blockIdx.x;
    int bs  = bid & (NBS - 1);         // B slice 0..31
    int at  = (bid >> 5) & (NAT - 1);  // A tile 0..1
    int b   = bid >> 6;                // batch
    int t   = threadIdx.x;
    int w   = t >> 5;
    int lane = t & 31;

    if (bid == 0 && t == 0) { out[0] = 0.0f; out[1] = 0.0f; }

    const float* Ab = A + b * 3 * NPTS;  // gts (tgt) — queries
    const float* Bb = B + b * 3 * NPTS;  // preds (src_transformed) — refs

    if (t < BSL) {
        int j = bs * BSL + t;
        float bx = Bb[j], by = Bb[NPTS + j], bz = Bb[2 * NPTS + j];
        float bn = fmaf(bx, bx, fmaf(by, by, bz * bz));
        sR1[t] = make_float4(bx, bx, by, by);
        sR2[t] = make_float4(bz, bz, bn, bn);
    }
    __syncthreads();

    // 8 queries per thread as 4 packed pairs; pre-scaled by -2; norms kept.
    float2 qx[4], qy[4], qz[4], qn[4];
    float  m[8];
    int i0 = at * ATILE + t;
    #pragma unroll
    for (int jp = 0; jp < 4; jp++) {
        int ia = i0 + (2 * jp) * TPB;
        int ic = i0 + (2 * jp + 1) * TPB;
        float ax = Ab[ia], ay = Ab[NPTS + ia], az = Ab[2 * NPTS + ia];
        float cx = Ab[ic], cy = Ab[NPTS + ic], cz = Ab[2 * NPTS + ic];
        qn[jp] = make_float2(fmaf(ax, ax, fmaf(ay, ay, az * az)),
                             fmaf(cx, cx, fmaf(cy, cy, cz * cz)));
        qx[jp] = make_float2(-2.0f * ax, -2.0f * cx);
        qy[jp] = make_float2(-2.0f * ay, -2.0f * cy);
        qz[jp] = make_float2(-2.0f * az, -2.0f * cz);
        m[2 * jp] = INFV; m[2 * jp + 1] = INFV;
    }

    #pragma unroll 4
    for (int i = 0; i < BSL; i++) {
        float4 r1 = sR1[i];                      // broadcast: 1 wavefront
        float4 r2 = sR2[i];
        float2 rx = make_float2(r1.x, r1.y);
        float2 ry = make_float2(r1.z, r1.w);
        float2 rz = make_float2(r2.x, r2.y);
        float2 rn = make_float2(r2.z, r2.w);

        float2 d0 = ffma2(qx[0], rx, ffma2(qy[0], ry, ffma2(qz[0], rz, fadd2(qn[0], rn))));
        float2 d1 = ffma2(qx[1], rx, ffma2(qy[1], ry, ffma2(qz[1], rz, fadd2(qn[1], rn))));
        float2 d2 = ffma2(qx[2], rx, ffma2(qy[2], ry, ffma2(qz[2], rz, fadd2(qn[2], rn))));
        float2 d3 = ffma2(qx[3], rx, ffma2(qy[3], ry, ffma2(qz[3], rz, fadd2(qn[3], rn))));

        m[0] = fminf(m[0], d0.x); m[1] = fminf(m[1], d0.y);
        m[2] = fminf(m[2], d1.x); m[3] = fminf(m[3], d1.y);
        m[4] = fminf(m[4], d2.x); m[5] = fminf(m[5], d2.y);
        m[6] = fminf(m[6], d3.x); m[7] = fminf(m[7], d3.y);

        // col min across the warp for ref i: tree -> clamp>=0 -> REDUX.MIN.U32
        float v0 = fminf(d0.x, d0.y);
        float v1 = fminf(d1.x, d1.y);
        float v2 = fminf(d2.x, d2.y);
        float v3 = fminf(d3.x, d3.y);
        float v  = fmaxf(fminf(fminf(v0, v1), fminf(v2, v3)), 0.0f);
        unsigned wm = __reduce_min_sync(0xffffffffu, __float_as_uint(v));
        if (lane == 0) cmin[w][i] = __uint_as_float(wm);
    }
    __syncthreads();

    // Row mins (full dists): encoded max-reduce (RED.MAX, no return).
    unsigned* rowm = g_minbits + b * NPTS;
    #pragma unroll
    for (int u = 0; u < 8; u++)
        atomicMax(&rowm[i0 + u * TPB], enc_desc(m[u]));

    // Col mins: merge 8 warp rows, one RED per B-point of this slice.
    if (t < BSL) {
        float cv = cmin[0][t];
        #pragma unroll
        for (int ww = 1; ww < 8; ww++) cv = fminf(cv, cmin[ww][t]);
        atomicMax(&g_minbits[BATCH * NPTS + b * NPTS + bs * BSL + t], enc_desc(cv));
    }
}

// ---------------------------------------------------------------------------
__device__ __forceinline__ float2 block_reduce2_128(float2 v) {
    __shared__ float2 sh[4];
    int lane = threadIdx.x & 31;
    int wid  = threadIdx.x >> 5;
    #pragma unroll
    for (int o = 16; o; o >>= 1) {
        v.x += __shfl_down_sync(0xffffffffu, v.x, o);
        v.y += __shfl_down_sync(0xffffffffu, v.y, o);
    }
    if (lane == 0) sh[wid] = v;
    __syncthreads();
    if (wid == 0) {
        v = (lane < 4) ? sh[lane] : make_float2(0.0f, 0.0f);
        #pragma unroll
        for (int o = 2; o; o >>= 1) {
            v.x += __shfl_down_sync(0xffffffffu, v.x, o);
            v.y += __shfl_down_sync(0xffffffffu, v.y, o);
        }
    }
    return v;
}

// ---------------------------------------------------------------------------
// Kernel 2: finalize. 512 blocks x 128 = 65536 threads; each thread does at
// most ONE knn float4-pair (gi < 49152), ONE min entry (gi < 32768), and the
// rare keypoint work (gi < 2048) — maximum parallelism, one latency round.
// ---------------------------------------------------------------------------
__global__ void __launch_bounds__(128) fin_kernel(const float* __restrict__ sk,
                                                  const float* __restrict__ tk,
                                                  const float* __restrict__ Rot,
                                                  const float* __restrict__ Tr,
                                                  const float* __restrict__ sknn,
                                                  const float* __restrict__ tknn,
                                                  float* __restrict__ out) {
    int gi = blockIdx.x * 128 + threadIdx.x;     // 0..65535

    const int TOT4 = BATCH * 3 * KPN * KNN / 4;  // 49152
    float h = 0.0f, acc = 0.0f;

    // knn consensus: one float4 pair per thread
    if (gi < TOT4) {
        float4 a0 = ((const float4*)sknn)[gi];
        float4 b0 = ((const float4*)tknn)[gi];
        float e0 = a0.x - b0.x, e1 = a0.y - b0.y, e2 = a0.z - b0.z, e3 = a0.w - b0.w;
        acc = fmaf(e0, e0, fmaf(e1, e1, fmaf(e2, e2, e3 * e3))) * (1.0f / (float)KNN);
    }

    // min entry -> huber
    if (gi < 2 * BATCH * NPTS) {
        unsigned e = g_minbits[gi];
        g_minbits[gi] = 0;                       // reset for next replay
        float d = dec_desc(e);
        const float c = 0.01f;
        h = (d < c) ? (0.5f * d * d) : fmaf(c, d, -0.5f * c * c);
    }

    // keypoint transform loss
    if (gi < BATCH * KPN) {
        int kb = gi >> 9;
        int p  = gi & (KPN - 1);
        const float* Rb  = Rot + kb * 9;
        const float* tb  = Tr + kb * 3;
        const float* skb = sk + kb * 3 * KPN;
        const float* tkb = tk + kb * 3 * KPN;
        float px = skb[p], py = skb[KPN + p], pz = skb[2 * KPN + p];
        #pragma unroll
        for (int cd = 0; cd < 3; cd++) {
            float wv = fmaf(Rb[cd * 3 + 0], px,
                       fmaf(Rb[cd * 3 + 1], py,
                       fmaf(Rb[cd * 3 + 2], pz, tb[cd])))
                       - tkb[cd * KPN + p];
            acc = fmaf(wv, wv, acc);
        }
    }

    float2 sums = block_reduce2_128(make_float2(acc, h));
    if (threadIdx.x == 0) {
        atomicAdd(&out[0], sums.x);
        atomicAdd(&out[1], sums.y);
    }
}

// ---------------------------------------------------------------------------
extern "C" void kernel_launch(void* const* d_in, const int* in_sizes, int n_in,
                              void* d_out, int out_size) {
    const float* src_kp  = (const float*)d_in[0];  // (B,3,KP)
    const float* tgt_kp  = (const float*)d_in[1];  // (B,3,KP)
    const float* rot     = (const float*)d_in[2];  // (B,3,3)
    const float* tra     = (const float*)d_in[3];  // (B,3)
    const float* src_knn = (const float*)d_in[4];  // (B,3,KP,K)
    const float* tgt_knn = (const float*)d_in[5];  // (B,3,KP,K)
    // d_in[6] = k (constant 32, hardcoded)
    const float* src_tr  = (const float*)d_in[7];  // (B,3,N) preds
    const float* tgt     = (const float*)d_in[8];  // (B,3,N) gts
    float* out = (float*)d_out;                    // out[0]=nbh, out[1]=gal

    min_kernel<<<NBLK, TPB>>>(tgt, src_tr, out);
    fin_kernel<<<512, 128>>>(src_kp, tgt_kp, rot, tra, src_knn, tgt_knn, out);
}

// round 15
// speedup vs baseline: 1.2065x; 1.0601x over previous
#include <cuda_runtime.h>

#define BATCH 4
#define NPTS  4096
#define KPN   512
#define KNN   32

#define TPB   256
#define BSL   128             // refs per block slice (inner loop length)
#define NBS   (NPTS / BSL)    // 32
#define ATILE 2048            // queries per block (8 per thread)
#define NAT   (NPTS / ATILE)  // 2
#define NBLK  (BATCH * NAT * NBS)  // 256 blocks
#define INFV  3.0e38f

// Encoded global mins: [0,16384) row (per-tgt-point), [16384,32768) col
// (per-src-point). Descending encoding => atomicMax == float-min, 0 == empty.
// Zero at module load; fin_kernel re-zeros each entry after reading.
__device__ unsigned g_minbits[2 * BATCH * NPTS];

__device__ __forceinline__ unsigned enc_desc(float f) {
    unsigned u = __float_as_uint(f);
    return (u & 0x80000000u) ? u : ~(u | 0x80000000u);
}
__device__ __forceinline__ float dec_desc(unsigned e) {
    unsigned s = ~e;
    unsigned u = (s & 0x80000000u) ? (s ^ 0x80000000u) : ~s;
    return __uint_as_float(u);
}

// Packed f32x2 ops (sm_103a, PTX-only; packed min does NOT exist)
__device__ __forceinline__ float2 ffma2(float2 a, float2 b, float2 c) {
    float2 d;
    asm("fma.rn.f32x2 %0, %1, %2, %3;"
        : "=l"(*reinterpret_cast<unsigned long long*>(&d))
        : "l"(*reinterpret_cast<const unsigned long long*>(&a)),
          "l"(*reinterpret_cast<const unsigned long long*>(&b)),
          "l"(*reinterpret_cast<const unsigned long long*>(&c)));
    return d;
}
__device__ __forceinline__ float2 fadd2(float2 a, float2 b) {
    float2 d;
    asm("add.rn.f32x2 %0, %1, %2;"
        : "=l"(*reinterpret_cast<unsigned long long*>(&d))
        : "l"(*reinterpret_cast<const unsigned long long*>(&a)),
          "l"(*reinterpret_cast<const unsigned long long*>(&b)));
    return d;
}

// ---------------------------------------------------------------------------
// Kernel 1 (R13, measured ~19.1us): dual-use tile pass, broadcast refs.
// Block = 2048 reg-resident queries (8/thread, packed, pre-scaled -2) x 128
// smem refs. Per iteration ALL lanes process the SAME ref (LDS broadcast, 1
// wavefront): 12 FFMA2 + 4 ADD2 (full-dist bias) + 8 row FMNMX + 7-min tree +
// clamp + one REDUX.MIN.U32 (dists >= 0 after clamp, so uint order == float
// order) + lane0 STS. No skew, no smem RMW chain.
// grid = BATCH * NAT * NBS = 256 blocks x 256 threads.
// ---------------------------------------------------------------------------
__global__ void __launch_bounds__(TPB) min_kernel(const float* __restrict__ A,
                                                  const float* __restrict__ B,
                                                  float* __restrict__ out) {
    __shared__ float4 sR1[BSL];        // (bx,bx,by,by)
    __shared__ float4 sR2[BSL];        // (bz,bz,bn,bn)
    __shared__ float  cmin[8][BSL];    // per-warp col mins (one STS/iter/warp)

    int bid = blockIdx.x;
    int bs  = bid & (NBS - 1);         // B slice 0..31
    int at  = (bid >> 5) & (NAT - 1);  // A tile 0..1
    int b   = bid >> 6;                // batch
    int t   = threadIdx.x;
    int w   = t >> 5;
    int lane = t & 31;

    if (bid == 0 && t == 0) { out[0] = 0.0f; out[1] = 0.0f; }

    const float* Ab = A + b * 3 * NPTS;  // gts (tgt) — queries
    const float* Bb = B + b * 3 * NPTS;  // preds (src_transformed) — refs

    if (t < BSL) {
        int j = bs * BSL + t;
        float bx = Bb[j], by = Bb[NPTS + j], bz = Bb[2 * NPTS + j];
        float bn = fmaf(bx, bx, fmaf(by, by, bz * bz));
        sR1[t] = make_float4(bx, bx, by, by);
        sR2[t] = make_float4(bz, bz, bn, bn);
    }
    __syncthreads();

    // 8 queries per thread as 4 packed pairs; pre-scaled by -2; norms kept.
    float2 qx[4], qy[4], qz[4], qn[4];
    float  m[8];
    int i0 = at * ATILE + t;
    #pragma unroll
    for (int jp = 0; jp < 4; jp++) {
        int ia = i0 + (2 * jp) * TPB;
        int ic = i0 + (2 * jp + 1) * TPB;
        float ax = Ab[ia], ay = Ab[NPTS + ia], az = Ab[2 * NPTS + ia];
        float cx = Ab[ic], cy = Ab[NPTS + ic], cz = Ab[2 * NPTS + ic];
        qn[jp] = make_float2(fmaf(ax, ax, fmaf(ay, ay, az * az)),
                             fmaf(cx, cx, fmaf(cy, cy, cz * cz)));
        qx[jp] = make_float2(-2.0f * ax, -2.0f * cx);
        qy[jp] = make_float2(-2.0f * ay, -2.0f * cy);
        qz[jp] = make_float2(-2.0f * az, -2.0f * cz);
        m[2 * jp] = INFV; m[2 * jp + 1] = INFV;
    }

    #pragma unroll 4
    for (int i = 0; i < BSL; i++) {
        float4 r1 = sR1[i];                      // broadcast: 1 wavefront
        float4 r2 = sR2[i];
        float2 rx = make_float2(r1.x, r1.y);
        float2 ry = make_float2(r1.z, r1.w);
        float2 rz = make_float2(r2.x, r2.y);
        float2 rn = make_float2(r2.z, r2.w);

        float2 d0 = ffma2(qx[0], rx, ffma2(qy[0], ry, ffma2(qz[0], rz, fadd2(qn[0], rn))));
        float2 d1 = ffma2(qx[1], rx, ffma2(qy[1], ry, ffma2(qz[1], rz, fadd2(qn[1], rn))));
        float2 d2 = ffma2(qx[2], rx, ffma2(qy[2], ry, ffma2(qz[2], rz, fadd2(qn[2], rn))));
        float2 d3 = ffma2(qx[3], rx, ffma2(qy[3], ry, ffma2(qz[3], rz, fadd2(qn[3], rn))));

        m[0] = fminf(m[0], d0.x); m[1] = fminf(m[1], d0.y);
        m[2] = fminf(m[2], d1.x); m[3] = fminf(m[3], d1.y);
        m[4] = fminf(m[4], d2.x); m[5] = fminf(m[5], d2.y);
        m[6] = fminf(m[6], d3.x); m[7] = fminf(m[7], d3.y);

        // col min across the warp for ref i: tree -> clamp>=0 -> REDUX.MIN.U32
        float v0 = fminf(d0.x, d0.y);
        float v1 = fminf(d1.x, d1.y);
        float v2 = fminf(d2.x, d2.y);
        float v3 = fminf(d3.x, d3.y);
        float v  = fmaxf(fminf(fminf(v0, v1), fminf(v2, v3)), 0.0f);
        unsigned wm = __reduce_min_sync(0xffffffffu, __float_as_uint(v));
        if (lane == 0) cmin[w][i] = __uint_as_float(wm);
    }
    __syncthreads();

    // Row mins (full dists): encoded max-reduce (RED.MAX, no return).
    unsigned* rowm = g_minbits + b * NPTS;
    #pragma unroll
    for (int u = 0; u < 8; u++)
        atomicMax(&rowm[i0 + u * TPB], enc_desc(m[u]));

    // Col mins: merge 8 warp rows, one RED per B-point of this slice.
    if (t < BSL) {
        float cv = cmin[0][t];
        #pragma unroll
        for (int ww = 1; ww < 8; ww++) cv = fminf(cv, cmin[ww][t]);
        atomicMax(&g_minbits[BATCH * NPTS + b * NPTS + bs * BSL + t], enc_desc(cv));
    }
}

// ---------------------------------------------------------------------------
__device__ __forceinline__ float2 block_reduce2(float2 v) {
    __shared__ float2 sh[32];
    int lane = threadIdx.x & 31;
    int wid  = threadIdx.x >> 5;
    #pragma unroll
    for (int o = 16; o; o >>= 1) {
        v.x += __shfl_down_sync(0xffffffffu, v.x, o);
        v.y += __shfl_down_sync(0xffffffffu, v.y, o);
    }
    if (lane == 0) sh[wid] = v;
    __syncthreads();
    if (wid == 0) {
        v = (lane < (int)(blockDim.x >> 5)) ? sh[lane] : make_float2(0.0f, 0.0f);
        #pragma unroll
        for (int o = 16; o; o >>= 1) {
            v.x += __shfl_down_sync(0xffffffffu, v.x, o);
            v.y += __shfl_down_sync(0xffffffffu, v.y, o);
        }
    }
    return v;
}

// ---------------------------------------------------------------------------
// Kernel 2 (R7, measured ~5.0us): finalize with all loads hoisted and
// independent. grid = 256 blocks x 128 threads = 32768 (one per min entry).
// ---------------------------------------------------------------------------
__global__ void __launch_bounds__(128) fin_kernel(const float* __restrict__ sk,
                                                  const float* __restrict__ tk,
                                                  const float* __restrict__ Rot,
                                                  const float* __restrict__ Tr,
                                                  const float* __restrict__ sknn,
                                                  const float* __restrict__ tknn,
                                                  float* __restrict__ out) {
    int i = blockIdx.x * 128 + threadIdx.x;  // 0..32767

    // -- issue all loads early, all independent --
    unsigned e = g_minbits[i];

    const int TOT4 = BATCH * 3 * KPN * KNN / 4;  // 49152
    const float4* s4 = (const float4*)sknn;
    const float4* t4 = (const float4*)tknn;
    float4 a0 = s4[i];
    float4 b0 = t4[i];
    bool has2 = (i + 32768) < TOT4;              // i < 16384
    int j2 = has2 ? (i + 32768) : i;
    float4 a1 = s4[j2];
    float4 b1 = t4[j2];

    g_minbits[i] = 0;                            // reset for next replay

    // -- huber on the min distance --
    float d = dec_desc(e);
    const float c = 0.01f;
    float h = (d < c) ? (0.5f * d * d) : fmaf(c, d, -0.5f * c * c);

    // -- knn consensus --
    float d0 = a0.x - b0.x, d1 = a0.y - b0.y, d2 = a0.z - b0.z, d3 = a0.w - b0.w;
    float acc = fmaf(d0, d0, fmaf(d1, d1, fmaf(d2, d2, d3 * d3)));
    if (has2) {
        float e0 = a1.x - b1.x, e1 = a1.y - b1.y, e2 = a1.z - b1.z, e3 = a1.w - b1.w;
        acc += fmaf(e0, e0, fmaf(e1, e1, fmaf(e2, e2, e3 * e3)));
    }
    acc *= (1.0f / (float)KNN);

    // -- keypoint transform loss (first 2048 threads) --
    if (i < BATCH * KPN) {
        int kb = i >> 9;
        int p  = i & (KPN - 1);
        const float* Rb  = Rot + kb * 9;
        const float* tb  = Tr + kb * 3;
        const float* skb = sk + kb * 3 * KPN;
        const float* tkb = tk + kb * 3 * KPN;
        float px = skb[p], py = skb[KPN + p], pz = skb[2 * KPN + p];
        #pragma unroll
        for (int cd = 0; cd < 3; cd++) {
            float wv = fmaf(Rb[cd * 3 + 0], px,
                       fmaf(Rb[cd * 3 + 1], py,
                       fmaf(Rb[cd * 3 + 2], pz, tb[cd])))
                       - tkb[cd * KPN + p];
            acc = fmaf(wv, wv, acc);
        }
    }

    float2 sums = block_reduce2(make_float2(acc, h));
    if (threadIdx.x == 0) {
        atomicAdd(&out[0], sums.x);
        atomicAdd(&out[1], sums.y);
    }
}

// ---------------------------------------------------------------------------
extern "C" void kernel_launch(void* const* d_in, const int* in_sizes, int n_in,
                              void* d_out, int out_size) {
    const float* src_kp  = (const float*)d_in[0];  // (B,3,KP)
    const float* tgt_kp  = (const float*)d_in[1];  // (B,3,KP)
    const float* rot     = (const float*)d_in[2];  // (B,3,3)
    const float* tra     = (const float*)d_in[3];  // (B,3)
    const float* src_knn = (const float*)d_in[4];  // (B,3,KP,K)
    const float* tgt_knn = (const float*)d_in[5];  // (B,3,KP,K)
    // d_in[6] = k (constant 32, hardcoded)
    const float* src_tr  = (const float*)d_in[7];  // (B,3,N) preds
    const float* tgt     = (const float*)d_in[8];  // (B,3,N) gts
    float* out = (float*)d_out;                    // out[0]=nbh, out[1]=gal

    min_kernel<<<NBLK, TPB>>>(tgt, src_tr, out);
    fin_kernel<<<256, 128>>>(src_kp, tgt_kp, rot, tra, src_knn, tgt_knn, out);
}

// round 17
// speedup vs baseline: 1.2080x; 1.0013x over previous
#include <cuda_runtime.h>

#define BATCH 4
#define NPTS  4096
#define KPN   512
#define KNN   32

#define TPB   256
#define BSL   128             // refs per block slice (inner loop length)
#define NBS   (NPTS / BSL)    // 32
#define ATILE 2048            // queries per block (8 per thread)
#define NAT   (NPTS / ATILE)  // 2
#define NBLK  (BATCH * NAT * NBS)  // 256 blocks
#define INFV  3.0e38f

// Encoded global mins: [0,16384) row (per-tgt-point), [16384,32768) col
// (per-src-point). Descending encoding => atomicMax == float-min, 0 == empty.
// Zero at module load; fin_kernel re-zeros each entry after reading.
__device__ unsigned g_minbits[2 * BATCH * NPTS];
// Per-block nbh partial sums (plain store each launch — no reset needed).
__device__ float    g_nbh[NBLK];

__device__ __forceinline__ unsigned enc_desc(float f) {
    unsigned u = __float_as_uint(f);
    return (u & 0x80000000u) ? u : ~(u | 0x80000000u);
}
__device__ __forceinline__ float dec_desc(unsigned e) {
    unsigned s = ~e;
    unsigned u = (s & 0x80000000u) ? (s ^ 0x80000000u) : ~s;
    return __uint_as_float(u);
}

// Packed f32x2 ops (sm_103a, PTX-only; packed min does NOT exist)
__device__ __forceinline__ float2 ffma2(float2 a, float2 b, float2 c) {
    float2 d;
    asm("fma.rn.f32x2 %0, %1, %2, %3;"
        : "=l"(*reinterpret_cast<unsigned long long*>(&d))
        : "l"(*reinterpret_cast<const unsigned long long*>(&a)),
          "l"(*reinterpret_cast<const unsigned long long*>(&b)),
          "l"(*reinterpret_cast<const unsigned long long*>(&c)));
    return d;
}
__device__ __forceinline__ float2 fadd2(float2 a, float2 b) {
    float2 d;
    asm("add.rn.f32x2 %0, %1, %2;"
        : "=l"(*reinterpret_cast<unsigned long long*>(&d))
        : "l"(*reinterpret_cast<const unsigned long long*>(&a)),
          "l"(*reinterpret_cast<const unsigned long long*>(&b)));
    return d;
}

__device__ __forceinline__ float block_reduce_sum(float v, float* sh) {
    int lane = threadIdx.x & 31;
    int wid  = threadIdx.x >> 5;
    #pragma unroll
    for (int o = 16; o; o >>= 1) v += __shfl_down_sync(0xffffffffu, v, o);
    if (lane == 0) sh[wid] = v;
    __syncthreads();
    if (wid == 0) {
        int nw = blockDim.x >> 5;
        v = (lane < nw) ? sh[lane] : 0.0f;
        #pragma unroll
        for (int o = 16; o; o >>= 1) v += __shfl_down_sync(0xffffffffu, v, o);
    }
    return v;
}

// ---------------------------------------------------------------------------
// Kernel 1: dual-use tile pass (measured-good R13/R15 loop) + overlapped nbh
// phase. Block = 2048 reg-resident queries (8/thread, packed, -2-prescaled) x
// 128 broadcast smem refs. Per iter: 2 LDS.128 (broadcast) + 12 FFMA2 +
// 4 ADD2 + row FMNMX + min tree + REDUX.MIN.U32 -> cmin. Epilogue: encoded
// RED.MAX row/col mins. Phase 2: knn + keypoint partials (independent of min
// results — hides inside other blocks' straggler spread), one slot per block.
// grid = 256 blocks x 256 threads.
// ---------------------------------------------------------------------------
__global__ void __launch_bounds__(TPB) min_kernel(const float* __restrict__ A,
                                                  const float* __restrict__ B,
                                                  const float* __restrict__ sk,
                                                  const float* __restrict__ tk,
                                                  const float* __restrict__ Rot,
                                                  const float* __restrict__ Tr,
                                                  const float* __restrict__ sknn,
                                                  const float* __restrict__ tknn,
                                                  float* __restrict__ out) {
    __shared__ float4 sR1[BSL];        // (bx,bx,by,by)
    __shared__ float4 sR2[BSL];        // (bz,bz,bn,bn)
    __shared__ float  cmin[8][BSL];    // per-warp col mins (one STS/iter/warp)
    __shared__ float  sred[32];        // reduction scratch

    int bid = blockIdx.x;
    int bs  = bid & (NBS - 1);         // B slice 0..31
    int at  = (bid >> 5) & (NAT - 1);  // A tile 0..1
    int b   = bid >> 6;                // batch
    int t   = threadIdx.x;
    int w   = t >> 5;
    int lane = t & 31;

    if (bid == 0 && t == 0) { out[0] = 0.0f; out[1] = 0.0f; }

    const float* Ab = A + b * 3 * NPTS;  // gts (tgt) — queries
    const float* Bb = B + b * 3 * NPTS;  // preds (src_transformed) — refs

    if (t < BSL) {
        int j = bs * BSL + t;
        float bx = Bb[j], by = Bb[NPTS + j], bz = Bb[2 * NPTS + j];
        float bn = fmaf(bx, bx, fmaf(by, by, bz * bz));
        sR1[t] = make_float4(bx, bx, by, by);
        sR2[t] = make_float4(bz, bz, bn, bn);
    }
    __syncthreads();

    // 8 queries per thread as 4 packed pairs; pre-scaled by -2; norms kept.
    float2 qx[4], qy[4], qz[4], qn[4];
    float  m[8];
    int i0 = at * ATILE + t;
    #pragma unroll
    for (int jp = 0; jp < 4; jp++) {
        int ia = i0 + (2 * jp) * TPB;
        int ic = i0 + (2 * jp + 1) * TPB;
        float ax = Ab[ia], ay = Ab[NPTS + ia], az = Ab[2 * NPTS + ia];
        float cx = Ab[ic], cy = Ab[NPTS + ic], cz = Ab[2 * NPTS + ic];
        qn[jp] = make_float2(fmaf(ax, ax, fmaf(ay, ay, az * az)),
                             fmaf(cx, cx, fmaf(cy, cy, cz * cz)));
        qx[jp] = make_float2(-2.0f * ax, -2.0f * cx);
        qy[jp] = make_float2(-2.0f * ay, -2.0f * cy);
        qz[jp] = make_float2(-2.0f * az, -2.0f * cz);
        m[2 * jp] = INFV; m[2 * jp + 1] = INFV;
    }

    #pragma unroll 4
    for (int i = 0; i < BSL; i++) {
        float4 r1 = sR1[i];                      // broadcast: 1 wavefront
        float4 r2 = sR2[i];
        float2 rx = make_float2(r1.x, r1.y);
        float2 ry = make_float2(r1.z, r1.w);
        float2 rz = make_float2(r2.x, r2.y);
        float2 rn = make_float2(r2.z, r2.w);

        float2 d0 = ffma2(qx[0], rx, ffma2(qy[0], ry, ffma2(qz[0], rz, fadd2(qn[0], rn))));
        float2 d1 = ffma2(qx[1], rx, ffma2(qy[1], ry, ffma2(qz[1], rz, fadd2(qn[1], rn))));
        float2 d2 = ffma2(qx[2], rx, ffma2(qy[2], ry, ffma2(qz[2], rz, fadd2(qn[2], rn))));
        float2 d3 = ffma2(qx[3], rx, ffma2(qy[3], ry, ffma2(qz[3], rz, fadd2(qn[3], rn))));

        m[0] = fminf(m[0], d0.x); m[1] = fminf(m[1], d0.y);
        m[2] = fminf(m[2], d1.x); m[3] = fminf(m[3], d1.y);
        m[4] = fminf(m[4], d2.x); m[5] = fminf(m[5], d2.y);
        m[6] = fminf(m[6], d3.x); m[7] = fminf(m[7], d3.y);

        // col min across the warp for ref i: tree -> clamp>=0 -> REDUX.MIN.U32
        float v0 = fminf(d0.x, d0.y);
        float v1 = fminf(d1.x, d1.y);
        float v2 = fminf(d2.x, d2.y);
        float v3 = fminf(d3.x, d3.y);
        float v  = fmaxf(fminf(fminf(v0, v1), fminf(v2, v3)), 0.0f);
        unsigned wm = __reduce_min_sync(0xffffffffu, __float_as_uint(v));
        if (lane == 0) cmin[w][i] = __uint_as_float(wm);
    }
    __syncthreads();

    // Row mins (full dists): encoded max-reduce (RED.MAX, no return).
    unsigned* rowm = g_minbits + b * NPTS;
    #pragma unroll
    for (int u = 0; u < 8; u++)
        atomicMax(&rowm[i0 + u * TPB], enc_desc(m[u]));

    // Col mins: merge 8 warp rows, one RED per B-point of this slice.
    if (t < BSL) {
        float cv = cmin[0][t];
        #pragma unroll
        for (int ww = 1; ww < 8; ww++) cv = fminf(cv, cmin[ww][t]);
        atomicMax(&g_minbits[BATCH * NPTS + b * NPTS + bs * BSL + t], enc_desc(cv));
    }

    // ---- Phase 2: nbh partial (independent of min results; overlaps other
    //      blocks' distance loops). 65536 threads cover 49152 float4 pairs. ----
    int gi = bid * TPB + t;
    float acc = 0.0f;
    const int TOT4 = BATCH * 3 * KPN * KNN / 4;  // 49152
    if (gi < TOT4) {
        float4 a0 = ((const float4*)sknn)[gi];
        float4 b0 = ((const float4*)tknn)[gi];
        float e0 = a0.x - b0.x, e1 = a0.y - b0.y, e2 = a0.z - b0.z, e3 = a0.w - b0.w;
        acc = fmaf(e0, e0, fmaf(e1, e1, fmaf(e2, e2, e3 * e3))) * (1.0f / (float)KNN);
    }
    if (gi < BATCH * KPN) {
        int kb = gi >> 9;
        int p  = gi & (KPN - 1);
        const float* Rb  = Rot + kb * 9;
        const float* tb  = Tr + kb * 3;
        const float* skb = sk + kb * 3 * KPN;
        const float* tkb = tk + kb * 3 * KPN;
        float px = skb[p], py = skb[KPN + p], pz = skb[2 * KPN + p];
        #pragma unroll
        for (int cd = 0; cd < 3; cd++) {
            float wv = fmaf(Rb[cd * 3 + 0], px,
                       fmaf(Rb[cd * 3 + 1], py,
                       fmaf(Rb[cd * 3 + 2], pz, tb[cd])))
                       - tkb[cd * KPN + p];
            acc = fmaf(wv, wv, acc);
        }
    }
    float s_nbh = block_reduce_sum(acc, sred);
    if (t == 0) g_nbh[bid] = s_nbh;    // plain store, overwritten each launch
}

// ---------------------------------------------------------------------------
// Kernel 2: light finalize. One thread per min entry: load, reset, huber,
// block-reduce. Each block also picks up exactly one nbh partial (g_nbh[bid]).
// grid = 256 blocks x 128 threads = 32768.
// ---------------------------------------------------------------------------
__global__ void __launch_bounds__(128) fin_kernel(float* __restrict__ out) {
    __shared__ float sred[32];
    int bid = blockIdx.x;
    int i = bid * 128 + threadIdx.x;   // 0..32767

    unsigned e = g_minbits[i];
    float nbh = (threadIdx.x == 0) ? g_nbh[bid] : 0.0f;
    g_minbits[i] = 0;                  // reset for next replay

    float d = dec_desc(e);
    const float c = 0.01f;
    float h = (d < c) ? (0.5f * d * d) : fmaf(c, d, -0.5f * c * c);

    float s = block_reduce_sum(h, sred);
    if (threadIdx.x == 0) {
        atomicAdd(&out[0], nbh);
        atomicAdd(&out[1], s);
    }
}

// ---------------------------------------------------------------------------
extern "C" void kernel_launch(void* const* d_in, const int* in_sizes, int n_in,
                              void* d_out, int out_size) {
    const float* src_kp  = (const float*)d_in[0];  // (B,3,KP)
    const float* tgt_kp  = (const float*)d_in[1];  // (B,3,KP)
    const float* rot     = (const float*)d_in[2];  // (B,3,3)
    const float* tra     = (const float*)d_in[3];  // (B,3)
    const float* src_knn = (const float*)d_in[4];  // (B,3,KP,K)
    const float* tgt_knn = (const float*)d_in[5];  // (B,3,KP,K)
    // d_in[6] = k (constant 32, hardcoded)
    const float* src_tr  = (const float*)d_in[7];  // (B,3,N) preds
    const float* tgt     = (const float*)d_in[8];  // (B,3,N) gts
    float* out = (float*)d_out;                    // out[0]=nbh, out[1]=gal

    min_kernel<<<NBLK, TPB>>>(tgt, src_tr, src_kp, tgt_kp, rot, tra,
                              src_knn, tgt_knn, out);
    fin_kernel<<<256, 128>>>(out);
}